// round 1
// baseline (speedup 1.0000x reference)
#include <cuda_runtime.h>
#include <math.h>

// Problem constants
#define BB   4
#define TT   3072
#define DD   1024
#define HH   16
#define HDIM 64
#define TKK  1025   // 1 + 3072/3

// -------- scratch (no cudaMalloc allowed) --------
__device__ float g_wt  [1024 * 3072];      // transposed conv weight [o][kw*1024+i]
__device__ float g_ktmp[BB * TKK * DD];    // concat(x[:, :1], conv_out)
__device__ float g_q   [BB * TT  * DD];
__device__ float g_k   [BB * TKK * DD];
__device__ float g_v   [BB * TKK * DD];
__device__ float g_att [BB * TT  * DD];    // attention output (b,t,d)

// ------------------------------------------------------------------
// Wconv (O, I, KW=3) -> g_wt (O, KW, I) so conv becomes a plain GEMM
// ------------------------------------------------------------------
__global__ void conv_w_transpose(const float* __restrict__ W, float* __restrict__ out) {
    int idx = blockIdx.x * 256 + threadIdx.x;     // over 1024*1024*3
    if (idx < 1024 * 1024 * 3) {
        int kw = idx % 3;
        int i  = (idx / 3) & 1023;
        int o  = idx / 3072;
        out[o * 3072 + kw * 1024 + i] = W[idx];
    }
}

// k_tmp[b, 0, :] = x[b, 0, :]
__global__ void copy_first_rows(const float* __restrict__ x, float* __restrict__ ktmp) {
    int idx = blockIdx.x * 256 + threadIdx.x;     // 4096 threads
    int b = idx >> 10, d = idx & 1023;
    ktmp[(size_t)b * TKK * DD + d] = x[(size_t)b * TT * DD + d];
}

// ------------------------------------------------------------------
// SGEMM:  C[m,n] = sum_k A[m,k] * W[n,k]  (+ bias[n])
// A: (M,K) row-major, W: (N,K) row-major (torch Linear weight).
// OUT_MODE 0: C[m*N+n]
// OUT_MODE 1: rows scattered into k_tmp layout: m -> (b=m>>10)*1025 + 1 + (m&1023)
// Tiling: 128x128x16, 256 threads, 8x8 per-thread micro-tile, reg prefetch.
// ------------------------------------------------------------------
template <int OUT_MODE, bool HAS_BIAS>
__global__ void __launch_bounds__(256)
sgemm_nt(const float* __restrict__ A, const float* __restrict__ W,
         const float* __restrict__ bias, float* __restrict__ C,
         int M, int N, int K) {
    __shared__ float As[16][128];
    __shared__ float Bs[16][128];

    const int tid = threadIdx.x;
    const int bm = blockIdx.y * 128;
    const int bn = blockIdx.x * 128;

    const int lrow = tid >> 1;            // 0..127
    const int lk   = (tid & 1) * 8;       // 0 or 8

    const int arow = bm + lrow;
    const int brow = bn + lrow;
    const bool aval = arow < M;
    const bool bval = brow < N;

    const float* Ap = A + (size_t)(aval ? arow : 0) * K + lk;
    const float* Bp = W + (size_t)(bval ? brow : 0) * K + lk;

    float4 pa0 = make_float4(0.f, 0.f, 0.f, 0.f), pa1 = pa0, pb0 = pa0, pb1 = pa0;
    if (aval) { pa0 = *(const float4*)(Ap);     pa1 = *(const float4*)(Ap + 4); }
    if (bval) { pb0 = *(const float4*)(Bp);     pb1 = *(const float4*)(Bp + 4); }

    const int ty = (tid >> 4) * 8;        // 0..120
    const int tx = (tid & 15) * 8;        // 0..120

    float acc[8][8];
#pragma unroll
    for (int i = 0; i < 8; i++)
#pragma unroll
        for (int j = 0; j < 8; j++) acc[i][j] = 0.f;

    for (int k0 = 0; k0 < K; k0 += 16) {
        __syncthreads();
        As[lk + 0][lrow] = pa0.x; As[lk + 1][lrow] = pa0.y;
        As[lk + 2][lrow] = pa0.z; As[lk + 3][lrow] = pa0.w;
        As[lk + 4][lrow] = pa1.x; As[lk + 5][lrow] = pa1.y;
        As[lk + 6][lrow] = pa1.z; As[lk + 7][lrow] = pa1.w;
        Bs[lk + 0][lrow] = pb0.x; Bs[lk + 1][lrow] = pb0.y;
        Bs[lk + 2][lrow] = pb0.z; Bs[lk + 3][lrow] = pb0.w;
        Bs[lk + 4][lrow] = pb1.x; Bs[lk + 5][lrow] = pb1.y;
        Bs[lk + 6][lrow] = pb1.z; Bs[lk + 7][lrow] = pb1.w;
        __syncthreads();

        const int kn = k0 + 16;
        if (kn < K) {
            if (aval) { pa0 = *(const float4*)(Ap + kn); pa1 = *(const float4*)(Ap + kn + 4); }
            if (bval) { pb0 = *(const float4*)(Bp + kn); pb1 = *(const float4*)(Bp + kn + 4); }
        }

#pragma unroll
        for (int kk = 0; kk < 16; kk++) {
            float ra[8], rb[8];
            *(float4*)(&ra[0]) = *(const float4*)(&As[kk][ty]);
            *(float4*)(&ra[4]) = *(const float4*)(&As[kk][ty + 4]);
            *(float4*)(&rb[0]) = *(const float4*)(&Bs[kk][tx]);
            *(float4*)(&rb[4]) = *(const float4*)(&Bs[kk][tx + 4]);
#pragma unroll
            for (int i = 0; i < 8; i++)
#pragma unroll
                for (int j = 0; j < 8; j++)
                    acc[i][j] = fmaf(ra[i], rb[j], acc[i][j]);
        }
    }

#pragma unroll
    for (int i = 0; i < 8; i++) {
        const int row = bm + ty + i;
        if (row >= M) continue;
        size_t rbase;
        if (OUT_MODE == 1) {
            const int b = row >> 10, r = row & 1023;
            rbase = ((size_t)b * TKK + 1 + r) * (size_t)N;
        } else {
            rbase = (size_t)row * (size_t)N;
        }
#pragma unroll
        for (int j = 0; j < 8; j++) {
            const int col = bn + tx + j;
            float val = acc[i][j];
            if (HAS_BIAS) val += bias[col];
            C[rbase + col] = val;
        }
    }
}

// ------------------------------------------------------------------
// Flash attention, fp32. Grid (48 q-tiles, 64 bh), 256 threads.
// 64 q-rows x 64 keys per tile, online softmax, mask: 3k <= q.
// Key 1024 is never attended (3*1024 > 3071), so key tiles run 0..15 only.
// smem: Qt[64][81] (transposed), Kt[64][81], Vs[64][64], Ss[64][65], resc/l[64].
// ------------------------------------------------------------------
#define ATT_PADT 81
#define ATT_PADS 65
#define ATT_SM_FLOATS (64*ATT_PADT*2 + 64*64 + 64*ATT_PADS + 128)
#define ATT_SM_BYTES  (ATT_SM_FLOATS * 4)

__global__ void __launch_bounds__(256)
attn_kernel(const float* __restrict__ Qg, const float* __restrict__ Kg,
            const float* __restrict__ Vg, float* __restrict__ Og) {
    extern __shared__ float sm[];
    float* Qt    = sm;                       // [64][81]  (d-major)
    float* Kt    = Qt + 64 * ATT_PADT;       // [64][81]  (d-major)
    float* Vs    = Kt + 64 * ATT_PADT;       // [64][64]  (key-major)
    float* Ss    = Vs + 64 * 64;             // [64][65]  (q-major)
    float* sresc = Ss + 64 * ATT_PADS;       // [64]
    float* slsum = sresc + 64;               // [64]

    const int tid = threadIdx.x;
    const int qb = blockIdx.x, bh = blockIdx.y;
    const int b = bh >> 4, h = bh & 15;

    const float* Qb = Qg + (size_t)b * TT  * DD + h * HDIM;
    const float* Kb = Kg + (size_t)b * TKK * DD + h * HDIM;
    const float* Vb = Vg + (size_t)b * TKK * DD + h * HDIM;
    float*       Ob = Og + (size_t)b * TT  * DD + h * HDIM;

    const int q0 = qb * 64;

    // load Q tile transposed (Qt[d][r])
#pragma unroll
    for (int rep = 0; rep < 16; rep++) {
        int e = rep * 256 + tid;
        int r = e >> 6, d = e & 63;
        Qt[d * ATT_PADT + r] = Qb[(size_t)(q0 + r) * DD + d];
    }

    const int r0 = (tid >> 4) * 4;   // 0..60
    const int c0 = (tid & 15) * 4;   // 0..60
    const int rowB = tid >> 2;       // 0..63
    const int segB = (tid & 3) * 16; // 0/16/32/48

    float acc[4][4];
#pragma unroll
    for (int i = 0; i < 4; i++)
#pragma unroll
        for (int j = 0; j < 4; j++) acc[i][j] = 0.f;
    float m_r = -1e30f, l_r = 0.f;

    const int nkb = ((q0 + 63) / 3) / 64 + 1;   // max 16

    for (int kb = 0; kb < nkb; kb++) {
        __syncthreads();   // previous phase C done with Ss/Vs
        const int kbase = kb * 64;
#pragma unroll
        for (int rep = 0; rep < 16; rep++) {
            int e = rep * 256 + tid;
            int r = e >> 6, d = e & 63;
            Kt[d * ATT_PADT + r] = Kb[(size_t)(kbase + r) * DD + d];
            Vs[r * 64 + d]       = Vb[(size_t)(kbase + r) * DD + d];
        }
        __syncthreads();

        // ---- phase A: S = Q K^T (4x4 per thread) ----
        float sacc[4][4];
#pragma unroll
        for (int i = 0; i < 4; i++)
#pragma unroll
            for (int j = 0; j < 4; j++) sacc[i][j] = 0.f;

#pragma unroll
        for (int d = 0; d < 64; d++) {
            float qa[4], ka[4];
#pragma unroll
            for (int i = 0; i < 4; i++) qa[i] = Qt[d * ATT_PADT + r0 + i];
#pragma unroll
            for (int j = 0; j < 4; j++) ka[j] = Kt[d * ATT_PADT + c0 + j];
#pragma unroll
            for (int i = 0; i < 4; i++)
#pragma unroll
                for (int j = 0; j < 4; j++)
                    sacc[i][j] = fmaf(qa[i], ka[j], sacc[i][j]);
        }
#pragma unroll
        for (int i = 0; i < 4; i++) {
            const int qg = q0 + r0 + i;
#pragma unroll
            for (int j = 0; j < 4; j++) {
                const int kg = kbase + c0 + j;
                Ss[(r0 + i) * ATT_PADS + c0 + j] =
                    (3 * kg <= qg) ? sacc[i][j] * 0.125f : -1e30f;
            }
        }
        __syncthreads();

        // ---- phase B: online softmax (4 threads per row) ----
        float tmax = -1e30f;
#pragma unroll
        for (int t = 0; t < 16; t++)
            tmax = fmaxf(tmax, Ss[rowB * ATT_PADS + segB + t]);
        tmax = fmaxf(tmax, __shfl_xor_sync(0xffffffffu, tmax, 1));
        tmax = fmaxf(tmax, __shfl_xor_sync(0xffffffffu, tmax, 2));
        const float mnew  = fmaxf(m_r, tmax);
        const float alpha = __expf(m_r - mnew);
        float psum = 0.f;
#pragma unroll
        for (int t = 0; t < 16; t++) {
            float p = __expf(Ss[rowB * ATT_PADS + segB + t] - mnew);
            Ss[rowB * ATT_PADS + segB + t] = p;
            psum += p;
        }
        psum += __shfl_xor_sync(0xffffffffu, psum, 1);
        psum += __shfl_xor_sync(0xffffffffu, psum, 2);
        l_r = l_r * alpha + psum;
        m_r = mnew;
        if ((tid & 3) == 0) sresc[rowB] = alpha;
        __syncthreads();

        // ---- phase C: O = O*alpha + P V ----
#pragma unroll
        for (int i = 0; i < 4; i++) {
            const float a = sresc[r0 + i];
#pragma unroll
            for (int j = 0; j < 4; j++) acc[i][j] *= a;
        }
#pragma unroll
        for (int k = 0; k < 64; k++) {
            float pv[4], vv[4];
#pragma unroll
            for (int i = 0; i < 4; i++) pv[i] = Ss[(r0 + i) * ATT_PADS + k];
#pragma unroll
            for (int j = 0; j < 4; j++) vv[j] = Vs[k * 64 + c0 + j];
#pragma unroll
            for (int i = 0; i < 4; i++)
#pragma unroll
                for (int j = 0; j < 4; j++)
                    acc[i][j] = fmaf(pv[i], vv[j], acc[i][j]);
        }
    }

    if ((tid & 3) == 0) slsum[rowB] = l_r;
    __syncthreads();

#pragma unroll
    for (int i = 0; i < 4; i++) {
        const float inv = 1.0f / slsum[r0 + i];
        float4 o4 = make_float4(acc[i][0] * inv, acc[i][1] * inv,
                                acc[i][2] * inv, acc[i][3] * inv);
        *(float4*)&Ob[(size_t)(q0 + r0 + i) * DD + c0] = o4;
    }
}

// ------------------------------------------------------------------
extern "C" void kernel_launch(void* const* d_in, const int* in_sizes, int n_in,
                              void* d_out, int out_size) {
    const float* x     = (const float*)d_in[0];
    const float* Wq    = (const float*)d_in[1];
    const float* Wk    = (const float*)d_in[2];
    const float* Wv    = (const float*)d_in[3];
    const float* Wo    = (const float*)d_in[4];
    const float* bo    = (const float*)d_in[5];
    const float* Wconv = (const float*)d_in[6];
    float* out = (float*)d_out;

    float *wt, *ktmp, *q, *k, *v, *att;
    cudaGetSymbolAddress((void**)&wt,   g_wt);
    cudaGetSymbolAddress((void**)&ktmp, g_ktmp);
    cudaGetSymbolAddress((void**)&q,    g_q);
    cudaGetSymbolAddress((void**)&k,    g_k);
    cudaGetSymbolAddress((void**)&v,    g_v);
    cudaGetSymbolAddress((void**)&att,  g_att);

    // 1. transpose conv weight
    conv_w_transpose<<<(1024 * 1024 * 3 + 255) / 256, 256>>>(Wconv, wt);
    // 2. k_tmp row 0 = x[:, 0, :]
    copy_first_rows<<<16, 256>>>(x, ktmp);
    // 3. conv as GEMM: (B*1024, 3072) x (1024, 3072)^T -> k_tmp rows 1..1024
    sgemm_nt<1, false><<<dim3(8, 32), 256>>>(x, wt, nullptr, ktmp, 4096, 1024, 3072);
    // 4. Q projection
    sgemm_nt<0, false><<<dim3(8, 96), 256>>>(x, Wq, nullptr, q, BB * TT, 1024, 1024);
    // 5/6. K, V projections over k_tmp (M = 4*1025 = 4100)
    sgemm_nt<0, false><<<dim3(8, 33), 256>>>(ktmp, Wk, nullptr, k, BB * TKK, 1024, 1024);
    sgemm_nt<0, false><<<dim3(8, 33), 256>>>(ktmp, Wv, nullptr, v, BB * TKK, 1024, 1024);
    // 7. attention
    cudaFuncSetAttribute(attn_kernel, cudaFuncAttributeMaxDynamicSharedMemorySize,
                         ATT_SM_BYTES);
    attn_kernel<<<dim3(48, 64), 256, ATT_SM_BYTES>>>(q, k, v, att);
    // 8. output projection + bias
    sgemm_nt<0, true><<<dim3(8, 96), 256>>>(att, Wo, bo, out, BB * TT, 1024, 1024);
}

// round 4
// speedup vs baseline: 1.8474x; 1.8474x over previous
#include <cuda_runtime.h>
#include <cuda_bf16.h>
#include <math.h>
#include <stdint.h>

// Problem constants
#define BB   4
#define TT   3072
#define DD   1024
#define HH   16
#define HDIM 64
#define TKK  1025   // 1 + 3072/3

// -------- scratch (no cudaMalloc allowed) --------
__device__ float g_wt  [1024 * 3072];      // transposed conv weight [o][kw*1024+i]
__device__ float g_ktmp[BB * TKK * DD];    // concat(x[:, :1], conv_out)
__device__ float g_q   [BB * TT  * DD];
__device__ float g_k   [BB * TKK * DD];
__device__ float g_v   [BB * TKK * DD];
__device__ float g_att [BB * TT  * DD];    // attention output (b,t,d)

static __device__ __forceinline__ uint32_t smem_u32(const void* p) {
    uint32_t a;
    asm("{ .reg .u64 t; cvta.to.shared.u64 t, %1; cvt.u32.u64 %0, t; }"
        : "=r"(a) : "l"(p));
    return a;
}

// mma.sync m16n8k16 row.col bf16 -> fp32 (baseline PTX, works on compute_103)
static __device__ __forceinline__ void mma16816(
    float* d, const uint32_t* a, uint32_t b0, uint32_t b1)
{
    asm volatile(
        "mma.sync.aligned.m16n8k16.row.col.f32.bf16.bf16.f32 "
        "{%0,%1,%2,%3}, {%4,%5,%6,%7}, {%8,%9}, {%0,%1,%2,%3};"
        : "+f"(d[0]), "+f"(d[1]), "+f"(d[2]), "+f"(d[3])
        : "r"(a[0]), "r"(a[1]), "r"(a[2]), "r"(a[3]), "r"(b0), "r"(b1));
}

static __device__ __forceinline__ void ldm4(uint32_t* r, uint32_t addr) {
    asm volatile(
        "ldmatrix.sync.aligned.m8n8.x4.shared.b16 {%0,%1,%2,%3}, [%4];"
        : "=r"(r[0]), "=r"(r[1]), "=r"(r[2]), "=r"(r[3]) : "r"(addr));
}

static __device__ __forceinline__ uint32_t packbf2(float x, float y) {
    __nv_bfloat162 t = __floats2bfloat162_rn(x, y);
    return *(uint32_t*)&t;
}

// split 8 fp32 into hi/lo bf16 pairs
static __device__ __forceinline__ void split8(float4 a, float4 b, uint4& hi, uint4& lo) {
    float f[8] = {a.x, a.y, a.z, a.w, b.x, b.y, b.z, b.w};
    float r[8];
#pragma unroll
    for (int i = 0; i < 8; i++) {
        __nv_bfloat16 h = __float2bfloat16_rn(f[i]);
        r[i] = f[i] - __bfloat162float(h);
    }
    hi.x = packbf2(f[0], f[1]); hi.y = packbf2(f[2], f[3]);
    hi.z = packbf2(f[4], f[5]); hi.w = packbf2(f[6], f[7]);
    lo.x = packbf2(r[0], r[1]); lo.y = packbf2(r[2], r[3]);
    lo.z = packbf2(r[4], r[5]); lo.w = packbf2(r[6], r[7]);
}

// ================= misc prep kernels =================
__global__ void conv_w_transpose(const float* __restrict__ W, float* __restrict__ out) {
    int idx = blockIdx.x * 256 + threadIdx.x;
    if (idx < 1024 * 1024 * 3) {
        int kw = idx % 3;
        int i  = (idx / 3) & 1023;
        int o  = idx / 3072;
        out[o * 3072 + kw * 1024 + i] = W[idx];
    }
}

__global__ void copy_first_rows(const float* __restrict__ x, float* __restrict__ ktmp) {
    int idx = blockIdx.x * 256 + threadIdx.x;
    int b = idx >> 10, d = idx & 1023;
    ktmp[(size_t)b * TKK * DD + d] = x[(size_t)b * TT * DD + d];
}

// ================================================================
// GEMM via mma.sync bf16-split: C[m,n] = sum_k A[m,k]*W[n,k] (+bias)
// Tile 128x128, K chunk = 64 fp32. 512 threads = 16 warps (4x4),
// warp tile 32x32 (2 m16-tiles x 4 n8-tiles).
// smem: Ahi/Alo/Bhi/Blo, each 128 rows x 144B (72 bf16, 64 used).
// ================================================================
#define GPITCH 144
#define GT_AHI 0
#define GT_ALO (128 * GPITCH)
#define GT_BHI (2 * 128 * GPITCH)
#define GT_BLO (3 * 128 * GPITCH)
#define G_SMEM (4 * 128 * GPITCH)

template <int OUT_MODE, bool HAS_BIAS>
__global__ void __launch_bounds__(512)
mma_gemm(const float* __restrict__ A, const float* __restrict__ W,
         const float* __restrict__ bias, float* __restrict__ C,
         int M, int N, int K) {
    extern __shared__ __align__(16) char smem[];
    const uint32_t sb = smem_u32(smem);

    const int tid  = threadIdx.x;
    const int lane = tid & 31;
    const int warp = tid >> 5;
    const int wm   = warp >> 2;     // 0..3
    const int wn   = warp & 3;      // 0..3
    const int bm   = blockIdx.y * 128;
    const int bn   = blockIdx.x * 128;

    // gmem load mapping: 2 "pairs" (8 fp32) per thread per matrix
    int rowP[2], kcP[2];
#pragma unroll
    for (int s = 0; s < 2; s++) {
        int p = s * 512 + tid;      // 0..1023
        rowP[s] = p >> 3;           // 0..127
        kcP[s]  = (p & 7) * 8;      // 0..56
    }

    // ldmatrix per-thread byte offsets
    uint32_t aoff[2], boff[2];
#pragma unroll
    for (int mi = 0; mi < 2; mi++) {
        int rowA = wm * 32 + mi * 16 + (lane & 15);
        aoff[mi] = (uint32_t)(rowA * GPITCH + ((lane >> 4) * 8) * 2);
    }
#pragma unroll
    for (int pi = 0; pi < 2; pi++) {
        int rowB = wn * 32 + pi * 16 + ((lane >> 4) << 3) + (lane & 7);
        boff[pi] = (uint32_t)(rowB * GPITCH + (((lane >> 3) & 1) * 8) * 2);
    }

    float acc[2][4][4];
#pragma unroll
    for (int mi = 0; mi < 2; mi++)
#pragma unroll
        for (int ni = 0; ni < 4; ni++)
#pragma unroll
            for (int t = 0; t < 4; t++) acc[mi][ni][t] = 0.f;

    const int nc = K >> 6;
    float4 a4[4], b4[4];

    // prologue: prefetch chunk 0
#pragma unroll
    for (int s = 0; s < 2; s++) {
        int ar = bm + rowP[s]; ar = ar < M ? ar : M - 1;
        const float* pa = A + (size_t)ar * K + kcP[s];
        a4[2 * s] = *(const float4*)pa; a4[2 * s + 1] = *(const float4*)(pa + 4);
        const float* pb = W + (size_t)(bn + rowP[s]) * K + kcP[s];
        b4[2 * s] = *(const float4*)pb; b4[2 * s + 1] = *(const float4*)(pb + 4);
    }

    for (int c = 0; c < nc; c++) {
        if (c) __syncthreads();
        // convert + store current chunk
#pragma unroll
        for (int s = 0; s < 2; s++) {
            const uint32_t off = (uint32_t)(rowP[s] * GPITCH + kcP[s] * 2);
            uint4 h, l;
            split8(a4[2 * s], a4[2 * s + 1], h, l);
            *(uint4*)(smem + GT_AHI + off) = h;
            *(uint4*)(smem + GT_ALO + off) = l;
            split8(b4[2 * s], b4[2 * s + 1], h, l);
            *(uint4*)(smem + GT_BHI + off) = h;
            *(uint4*)(smem + GT_BLO + off) = l;
        }
        __syncthreads();

        // prefetch next chunk while mma runs
        if (c + 1 < nc) {
            const int kb = (c + 1) << 6;
#pragma unroll
            for (int s = 0; s < 2; s++) {
                int ar = bm + rowP[s]; ar = ar < M ? ar : M - 1;
                const float* pa = A + (size_t)ar * K + kb + kcP[s];
                a4[2 * s] = *(const float4*)pa; a4[2 * s + 1] = *(const float4*)(pa + 4);
                const float* pb = W + (size_t)(bn + rowP[s]) * K + kb + kcP[s];
                b4[2 * s] = *(const float4*)pb; b4[2 * s + 1] = *(const float4*)(pb + 4);
            }
        }

        // 4 k16 steps
#pragma unroll
        for (int kk = 0; kk < 4; kk++) {
            const uint32_t ko = (uint32_t)(kk * 32);   // 16 bf16 * 2B
            uint32_t ah[2][4], al[2][4], bh[2][4], bl[2][4];
            ldm4(ah[0], sb + GT_AHI + aoff[0] + ko);
            ldm4(ah[1], sb + GT_AHI + aoff[1] + ko);
            ldm4(bh[0], sb + GT_BHI + boff[0] + ko);
            ldm4(bh[1], sb + GT_BHI + boff[1] + ko);
            ldm4(al[0], sb + GT_ALO + aoff[0] + ko);
            ldm4(al[1], sb + GT_ALO + aoff[1] + ko);
            ldm4(bl[0], sb + GT_BLO + boff[0] + ko);
            ldm4(bl[1], sb + GT_BLO + boff[1] + ko);
#pragma unroll
            for (int mi = 0; mi < 2; mi++)
#pragma unroll
                for (int ni = 0; ni < 4; ni++) {
                    const int pr = ni >> 1, ix = (ni & 1) * 2;
                    mma16816(acc[mi][ni], ah[mi], bh[pr][ix], bh[pr][ix + 1]);
                    mma16816(acc[mi][ni], ah[mi], bl[pr][ix], bl[pr][ix + 1]);
                    mma16816(acc[mi][ni], al[mi], bh[pr][ix], bh[pr][ix + 1]);
                }
        }
    }

    // epilogue
#pragma unroll
    for (int mi = 0; mi < 2; mi++) {
#pragma unroll
        for (int ni = 0; ni < 4; ni++) {
            const int col = bn + wn * 32 + ni * 8 + (lane & 3) * 2;
            float2 v0 = make_float2(acc[mi][ni][0], acc[mi][ni][1]);
            float2 v1 = make_float2(acc[mi][ni][2], acc[mi][ni][3]);
            if (HAS_BIAS) {
                const float bx = bias[col], by = bias[col + 1];
                v0.x += bx; v0.y += by; v1.x += bx; v1.y += by;
            }
            const int r0 = bm + wm * 32 + mi * 16 + (lane >> 2);
            const int r1 = r0 + 8;
            if (r0 < M) {
                size_t rb;
                if (OUT_MODE == 1) {
                    const int b = r0 >> 10, rr = r0 & 1023;
                    rb = ((size_t)b * TKK + 1 + rr) * (size_t)N;
                } else rb = (size_t)r0 * (size_t)N;
                *(float2*)&C[rb + col] = v0;
            }
            if (r1 < M) {
                size_t rb;
                if (OUT_MODE == 1) {
                    const int b = r1 >> 10, rr = r1 & 1023;
                    rb = ((size_t)b * TKK + 1 + rr) * (size_t)N;
                } else rb = (size_t)r1 * (size_t)N;
                *(float2*)&C[rb + col] = v1;
            }
        }
    }
}

// ------------------------------------------------------------------
// Flash attention, fp32 (round-1 proven version).
// ------------------------------------------------------------------
#define ATT_PADT 81
#define ATT_PADS 65
#define ATT_SM_FLOATS (64*ATT_PADT*2 + 64*64 + 64*ATT_PADS + 128)
#define ATT_SM_BYTES  (ATT_SM_FLOATS * 4)

__global__ void __launch_bounds__(256)
attn_kernel(const float* __restrict__ Qg, const float* __restrict__ Kg,
            const float* __restrict__ Vg, float* __restrict__ Og) {
    extern __shared__ float sm[];
    float* Qt    = sm;
    float* Kt    = Qt + 64 * ATT_PADT;
    float* Vs    = Kt + 64 * ATT_PADT;
    float* Ss    = Vs + 64 * 64;
    float* sresc = Ss + 64 * ATT_PADS;
    float* slsum = sresc + 64;

    const int tid = threadIdx.x;
    const int qb = blockIdx.x, bh = blockIdx.y;
    const int b = bh >> 4, h = bh & 15;

    const float* Qb = Qg + (size_t)b * TT  * DD + h * HDIM;
    const float* Kb = Kg + (size_t)b * TKK * DD + h * HDIM;
    const float* Vb = Vg + (size_t)b * TKK * DD + h * HDIM;
    float*       Ob = Og + (size_t)b * TT  * DD + h * HDIM;

    const int q0 = qb * 64;

#pragma unroll
    for (int rep = 0; rep < 16; rep++) {
        int e = rep * 256 + tid;
        int r = e >> 6, d = e & 63;
        Qt[d * ATT_PADT + r] = Qb[(size_t)(q0 + r) * DD + d];
    }

    const int r0 = (tid >> 4) * 4;
    const int c0 = (tid & 15) * 4;
    const int rowB = tid >> 2;
    const int segB = (tid & 3) * 16;

    float acc[4][4];
#pragma unroll
    for (int i = 0; i < 4; i++)
#pragma unroll
        for (int j = 0; j < 4; j++) acc[i][j] = 0.f;
    float m_r = -1e30f, l_r = 0.f;

    const int nkb = ((q0 + 63) / 3) / 64 + 1;

    for (int kb = 0; kb < nkb; kb++) {
        __syncthreads();
        const int kbase = kb * 64;
#pragma unroll
        for (int rep = 0; rep < 16; rep++) {
            int e = rep * 256 + tid;
            int r = e >> 6, d = e & 63;
            Kt[d * ATT_PADT + r] = Kb[(size_t)(kbase + r) * DD + d];
            Vs[r * 64 + d]       = Vb[(size_t)(kbase + r) * DD + d];
        }
        __syncthreads();

        float sacc[4][4];
#pragma unroll
        for (int i = 0; i < 4; i++)
#pragma unroll
            for (int j = 0; j < 4; j++) sacc[i][j] = 0.f;

#pragma unroll
        for (int d = 0; d < 64; d++) {
            float qa[4], ka[4];
#pragma unroll
            for (int i = 0; i < 4; i++) qa[i] = Qt[d * ATT_PADT + r0 + i];
#pragma unroll
            for (int j = 0; j < 4; j++) ka[j] = Kt[d * ATT_PADT + c0 + j];
#pragma unroll
            for (int i = 0; i < 4; i++)
#pragma unroll
                for (int j = 0; j < 4; j++)
                    sacc[i][j] = fmaf(qa[i], ka[j], sacc[i][j]);
        }
#pragma unroll
        for (int i = 0; i < 4; i++) {
            const int qg = q0 + r0 + i;
#pragma unroll
            for (int j = 0; j < 4; j++) {
                const int kg = kbase + c0 + j;
                Ss[(r0 + i) * ATT_PADS + c0 + j] =
                    (3 * kg <= qg) ? sacc[i][j] * 0.125f : -1e30f;
            }
        }
        __syncthreads();

        float tmax = -1e30f;
#pragma unroll
        for (int t = 0; t < 16; t++)
            tmax = fmaxf(tmax, Ss[rowB * ATT_PADS + segB + t]);
        tmax = fmaxf(tmax, __shfl_xor_sync(0xffffffffu, tmax, 1));
        tmax = fmaxf(tmax, __shfl_xor_sync(0xffffffffu, tmax, 2));
        const float mnew  = fmaxf(m_r, tmax);
        const float alpha = __expf(m_r - mnew);
        float psum = 0.f;
#pragma unroll
        for (int t = 0; t < 16; t++) {
            float p = __expf(Ss[rowB * ATT_PADS + segB + t] - mnew);
            Ss[rowB * ATT_PADS + segB + t] = p;
            psum += p;
        }
        psum += __shfl_xor_sync(0xffffffffu, psum, 1);
        psum += __shfl_xor_sync(0xffffffffu, psum, 2);
        l_r = l_r * alpha + psum;
        m_r = mnew;
        if ((tid & 3) == 0) sresc[rowB] = alpha;
        __syncthreads();

#pragma unroll
        for (int i = 0; i < 4; i++) {
            const float a = sresc[r0 + i];
#pragma unroll
            for (int j = 0; j < 4; j++) acc[i][j] *= a;
        }
#pragma unroll
        for (int k = 0; k < 64; k++) {
            float pv[4], vv[4];
#pragma unroll
            for (int i = 0; i < 4; i++) pv[i] = Ss[(r0 + i) * ATT_PADS + k];
#pragma unroll
            for (int j = 0; j < 4; j++) vv[j] = Vs[k * 64 + c0 + j];
#pragma unroll
            for (int i = 0; i < 4; i++)
#pragma unroll
                for (int j = 0; j < 4; j++)
                    acc[i][j] = fmaf(pv[i], vv[j], acc[i][j]);
        }
    }

    if ((tid & 3) == 0) slsum[rowB] = l_r;
    __syncthreads();

#pragma unroll
    for (int i = 0; i < 4; i++) {
        const float inv = 1.0f / slsum[r0 + i];
        float4 o4 = make_float4(acc[i][0] * inv, acc[i][1] * inv,
                                acc[i][2] * inv, acc[i][3] * inv);
        *(float4*)&Ob[(size_t)(q0 + r0 + i) * DD + c0] = o4;
    }
}

// ------------------------------------------------------------------
extern "C" void kernel_launch(void* const* d_in, const int* in_sizes, int n_in,
                              void* d_out, int out_size) {
    const float* x     = (const float*)d_in[0];
    const float* Wq    = (const float*)d_in[1];
    const float* Wk    = (const float*)d_in[2];
    const float* Wv    = (const float*)d_in[3];
    const float* Wo    = (const float*)d_in[4];
    const float* bo    = (const float*)d_in[5];
    const float* Wconv = (const float*)d_in[6];
    float* out = (float*)d_out;

    float *wt, *ktmp, *q, *k, *v, *att;
    cudaGetSymbolAddress((void**)&wt,   g_wt);
    cudaGetSymbolAddress((void**)&ktmp, g_ktmp);
    cudaGetSymbolAddress((void**)&q,    g_q);
    cudaGetSymbolAddress((void**)&k,    g_k);
    cudaGetSymbolAddress((void**)&v,    g_v);
    cudaGetSymbolAddress((void**)&att,  g_att);

    cudaFuncSetAttribute(mma_gemm<0, false>,
                         cudaFuncAttributeMaxDynamicSharedMemorySize, G_SMEM);
    cudaFuncSetAttribute(mma_gemm<1, false>,
                         cudaFuncAttributeMaxDynamicSharedMemorySize, G_SMEM);
    cudaFuncSetAttribute(mma_gemm<0, true>,
                         cudaFuncAttributeMaxDynamicSharedMemorySize, G_SMEM);
    cudaFuncSetAttribute(attn_kernel,
                         cudaFuncAttributeMaxDynamicSharedMemorySize, ATT_SM_BYTES);

    // 1. transpose conv weight
    conv_w_transpose<<<(1024 * 1024 * 3 + 255) / 256, 256>>>(Wconv, wt);
    // 2. k_tmp row 0 = x[:, 0, :]
    copy_first_rows<<<16, 256>>>(x, ktmp);
    // 3. conv as GEMM: x viewed as (4096, 3072) @ wt^T -> k_tmp rows 1..1024
    mma_gemm<1, false><<<dim3(8, 32), 512, G_SMEM>>>(x, wt, nullptr, ktmp, 4096, 1024, 3072);
    // 4. Q projection  (M = 12288 -> 96 M-tiles!)
    mma_gemm<0, false><<<dim3(8, 96), 512, G_SMEM>>>(x, Wq, nullptr, q, BB * TT, 1024, 1024);
    // 5/6. K, V projections over k_tmp (M = 4100)
    mma_gemm<0, false><<<dim3(8, 33), 512, G_SMEM>>>(ktmp, Wk, nullptr, k, BB * TKK, 1024, 1024);
    mma_gemm<0, false><<<dim3(8, 33), 512, G_SMEM>>>(ktmp, Wv, nullptr, v, BB * TKK, 1024, 1024);
    // 7. attention (fp32)
    attn_kernel<<<dim3(48, 64), 256, ATT_SM_BYTES>>>(q, k, v, att);
    // 8. output projection + bias  (M = 12288 -> 96 M-tiles!)
    mma_gemm<0, true><<<dim3(8, 96), 512, G_SMEM>>>(att, Wo, bo, out, BB * TT, 1024, 1024);
}

// round 5
// speedup vs baseline: 2.5338x; 1.3716x over previous
#include <cuda_runtime.h>
#include <cuda_bf16.h>
#include <math.h>
#include <stdint.h>

// Problem constants
#define BB   4
#define TT   3072
#define DD   1024
#define HH   16
#define HDIM 64
#define TKK  1025   // 1 + 3072/3

// -------- scratch (no cudaMalloc allowed) --------
__device__ float g_wt  [1024 * 3072];
__device__ float g_ktmp[BB * TKK * DD];
__device__ float g_q   [BB * TT  * DD];
__device__ float g_k   [BB * TKK * DD];
__device__ float g_v   [BB * TKK * DD];
__device__ float g_att [BB * TT  * DD];

static __device__ __forceinline__ uint32_t smem_u32(const void* p) {
    uint32_t a;
    asm("{ .reg .u64 t; cvta.to.shared.u64 t, %1; cvt.u32.u64 %0, t; }"
        : "=r"(a) : "l"(p));
    return a;
}

static __device__ __forceinline__ void mma16816(
    float* d, const uint32_t* a, uint32_t b0, uint32_t b1)
{
    asm volatile(
        "mma.sync.aligned.m16n8k16.row.col.f32.bf16.bf16.f32 "
        "{%0,%1,%2,%3}, {%4,%5,%6,%7}, {%8,%9}, {%0,%1,%2,%3};"
        : "+f"(d[0]), "+f"(d[1]), "+f"(d[2]), "+f"(d[3])
        : "r"(a[0]), "r"(a[1]), "r"(a[2]), "r"(a[3]), "r"(b0), "r"(b1));
}

static __device__ __forceinline__ void ldm4(uint32_t* r, uint32_t addr) {
    asm volatile(
        "ldmatrix.sync.aligned.m8n8.x4.shared.b16 {%0,%1,%2,%3}, [%4];"
        : "=r"(r[0]), "=r"(r[1]), "=r"(r[2]), "=r"(r[3]) : "r"(addr));
}

static __device__ __forceinline__ void ldm4t(uint32_t* r, uint32_t addr) {
    asm volatile(
        "ldmatrix.sync.aligned.m8n8.x4.trans.shared.b16 {%0,%1,%2,%3}, [%4];"
        : "=r"(r[0]), "=r"(r[1]), "=r"(r[2]), "=r"(r[3]) : "r"(addr));
}

static __device__ __forceinline__ uint32_t packbf2(float x, float y) {
    __nv_bfloat162 t = __floats2bfloat162_rn(x, y);
    return *(uint32_t*)&t;
}

static __device__ __forceinline__ void split8(float4 a, float4 b, uint4& hi, uint4& lo) {
    float f[8] = {a.x, a.y, a.z, a.w, b.x, b.y, b.z, b.w};
    float r[8];
#pragma unroll
    for (int i = 0; i < 8; i++) {
        __nv_bfloat16 h = __float2bfloat16_rn(f[i]);
        r[i] = f[i] - __bfloat162float(h);
    }
    hi.x = packbf2(f[0], f[1]); hi.y = packbf2(f[2], f[3]);
    hi.z = packbf2(f[4], f[5]); hi.w = packbf2(f[6], f[7]);
    lo.x = packbf2(r[0], r[1]); lo.y = packbf2(r[2], r[3]);
    lo.z = packbf2(r[4], r[5]); lo.w = packbf2(r[6], r[7]);
}

static __device__ __forceinline__ void split2(float a, float b, uint32_t& hi, uint32_t& lo) {
    __nv_bfloat16 ha = __float2bfloat16_rn(a);
    __nv_bfloat16 hb = __float2bfloat16_rn(b);
    hi = ((uint32_t)__bfloat16_as_ushort(hb) << 16) | (uint32_t)__bfloat16_as_ushort(ha);
    lo = packbf2(a - __bfloat162float(ha), b - __bfloat162float(hb));
}

// ================= misc prep kernels =================
__global__ void conv_w_transpose(const float* __restrict__ W, float* __restrict__ out) {
    int idx = blockIdx.x * 256 + threadIdx.x;
    if (idx < 1024 * 1024 * 3) {
        int kw = idx % 3;
        int i  = (idx / 3) & 1023;
        int o  = idx / 3072;
        out[o * 3072 + kw * 1024 + i] = W[idx];
    }
}

__global__ void copy_first_rows(const float* __restrict__ x, float* __restrict__ ktmp) {
    int idx = blockIdx.x * 256 + threadIdx.x;
    int b = idx >> 10, d = idx & 1023;
    ktmp[(size_t)b * TKK * DD + d] = x[(size_t)b * TT * DD + d];
}

// ================================================================
// GEMM via mma.sync bf16-split (proven in round 4, unchanged)
// ================================================================
#define GPITCH 144
#define GT_AHI 0
#define GT_ALO (128 * GPITCH)
#define GT_BHI (2 * 128 * GPITCH)
#define GT_BLO (3 * 128 * GPITCH)
#define G_SMEM (4 * 128 * GPITCH)

template <int OUT_MODE, bool HAS_BIAS>
__global__ void __launch_bounds__(512)
mma_gemm(const float* __restrict__ A, const float* __restrict__ W,
         const float* __restrict__ bias, float* __restrict__ C,
         int M, int N, int K) {
    extern __shared__ __align__(16) char smem[];
    const uint32_t sb = smem_u32(smem);

    const int tid  = threadIdx.x;
    const int lane = tid & 31;
    const int warp = tid >> 5;
    const int wm   = warp >> 2;
    const int wn   = warp & 3;
    const int bm   = blockIdx.y * 128;
    const int bn   = blockIdx.x * 128;

    int rowP[2], kcP[2];
#pragma unroll
    for (int s = 0; s < 2; s++) {
        int p = s * 512 + tid;
        rowP[s] = p >> 3;
        kcP[s]  = (p & 7) * 8;
    }

    uint32_t aoff[2], boff[2];
#pragma unroll
    for (int mi = 0; mi < 2; mi++) {
        int rowA = wm * 32 + mi * 16 + (lane & 15);
        aoff[mi] = (uint32_t)(rowA * GPITCH + ((lane >> 4) * 8) * 2);
    }
#pragma unroll
    for (int pi = 0; pi < 2; pi++) {
        int rowB = wn * 32 + pi * 16 + ((lane >> 4) << 3) + (lane & 7);
        boff[pi] = (uint32_t)(rowB * GPITCH + (((lane >> 3) & 1) * 8) * 2);
    }

    float acc[2][4][4];
#pragma unroll
    for (int mi = 0; mi < 2; mi++)
#pragma unroll
        for (int ni = 0; ni < 4; ni++)
#pragma unroll
            for (int t = 0; t < 4; t++) acc[mi][ni][t] = 0.f;

    const int nc = K >> 6;
    float4 a4[4], b4[4];

#pragma unroll
    for (int s = 0; s < 2; s++) {
        int ar = bm + rowP[s]; ar = ar < M ? ar : M - 1;
        const float* pa = A + (size_t)ar * K + kcP[s];
        a4[2 * s] = *(const float4*)pa; a4[2 * s + 1] = *(const float4*)(pa + 4);
        const float* pb = W + (size_t)(bn + rowP[s]) * K + kcP[s];
        b4[2 * s] = *(const float4*)pb; b4[2 * s + 1] = *(const float4*)(pb + 4);
    }

    for (int c = 0; c < nc; c++) {
        if (c) __syncthreads();
#pragma unroll
        for (int s = 0; s < 2; s++) {
            const uint32_t off = (uint32_t)(rowP[s] * GPITCH + kcP[s] * 2);
            uint4 h, l;
            split8(a4[2 * s], a4[2 * s + 1], h, l);
            *(uint4*)(smem + GT_AHI + off) = h;
            *(uint4*)(smem + GT_ALO + off) = l;
            split8(b4[2 * s], b4[2 * s + 1], h, l);
            *(uint4*)(smem + GT_BHI + off) = h;
            *(uint4*)(smem + GT_BLO + off) = l;
        }
        __syncthreads();

        if (c + 1 < nc) {
            const int kb = (c + 1) << 6;
#pragma unroll
            for (int s = 0; s < 2; s++) {
                int ar = bm + rowP[s]; ar = ar < M ? ar : M - 1;
                const float* pa = A + (size_t)ar * K + kb + kcP[s];
                a4[2 * s] = *(const float4*)pa; a4[2 * s + 1] = *(const float4*)(pa + 4);
                const float* pb = W + (size_t)(bn + rowP[s]) * K + kb + kcP[s];
                b4[2 * s] = *(const float4*)pb; b4[2 * s + 1] = *(const float4*)(pb + 4);
            }
        }

#pragma unroll
        for (int kk = 0; kk < 4; kk++) {
            const uint32_t ko = (uint32_t)(kk * 32);
            uint32_t ah[2][4], al[2][4], bh[2][4], bl[2][4];
            ldm4(ah[0], sb + GT_AHI + aoff[0] + ko);
            ldm4(ah[1], sb + GT_AHI + aoff[1] + ko);
            ldm4(bh[0], sb + GT_BHI + boff[0] + ko);
            ldm4(bh[1], sb + GT_BHI + boff[1] + ko);
            ldm4(al[0], sb + GT_ALO + aoff[0] + ko);
            ldm4(al[1], sb + GT_ALO + aoff[1] + ko);
            ldm4(bl[0], sb + GT_BLO + boff[0] + ko);
            ldm4(bl[1], sb + GT_BLO + boff[1] + ko);
#pragma unroll
            for (int mi = 0; mi < 2; mi++)
#pragma unroll
                for (int ni = 0; ni < 4; ni++) {
                    const int pr = ni >> 1, ix = (ni & 1) * 2;
                    mma16816(acc[mi][ni], ah[mi], bh[pr][ix], bh[pr][ix + 1]);
                    mma16816(acc[mi][ni], ah[mi], bl[pr][ix], bl[pr][ix + 1]);
                    mma16816(acc[mi][ni], al[mi], bh[pr][ix], bh[pr][ix + 1]);
                }
        }
    }

#pragma unroll
    for (int mi = 0; mi < 2; mi++) {
#pragma unroll
        for (int ni = 0; ni < 4; ni++) {
            const int col = bn + wn * 32 + ni * 8 + (lane & 3) * 2;
            float2 v0 = make_float2(acc[mi][ni][0], acc[mi][ni][1]);
            float2 v1 = make_float2(acc[mi][ni][2], acc[mi][ni][3]);
            if (HAS_BIAS) {
                const float bx = bias[col], by = bias[col + 1];
                v0.x += bx; v0.y += by; v1.x += bx; v1.y += by;
            }
            const int r0 = bm + wm * 32 + mi * 16 + (lane >> 2);
            const int r1 = r0 + 8;
            if (r0 < M) {
                size_t rb;
                if (OUT_MODE == 1) {
                    const int b = r0 >> 10, rr = r0 & 1023;
                    rb = ((size_t)b * TKK + 1 + rr) * (size_t)N;
                } else rb = (size_t)r0 * (size_t)N;
                *(float2*)&C[rb + col] = v0;
            }
            if (r1 < M) {
                size_t rb;
                if (OUT_MODE == 1) {
                    const int b = r1 >> 10, rr = r1 & 1023;
                    rb = ((size_t)b * TKK + 1 + rr) * (size_t)N;
                } else rb = (size_t)r1 * (size_t)N;
                *(float2*)&C[rb + col] = v1;
            }
        }
    }
}

// ================================================================
// Flash attention via mma.sync bf16-split.
// Grid (24 q-blocks of 128 rows, 64 bh). 256 threads = 8 warps,
// warp w owns q rows q0 + 16w .. +15.
// smem: Khi/Klo/Vhi/Vlo each [64 rows][144B] (64 bf16 + pad).
// Q frags hoisted (staged through K/V buffers before the key loop).
// S = Q K^T: 3-product hi/lo. P V: P split in-register (S-acc layout
// == A-frag layout), V via ldmatrix.trans, 3-product.
// ================================================================
#define APITCH 144
#define A_SKH 0
#define A_SKL (64 * APITCH)
#define A_SVH (2 * 64 * APITCH)
#define A_SVL (3 * 64 * APITCH)

__global__ void __launch_bounds__(256)
attn_mma(const float* __restrict__ Qg, const float* __restrict__ Kg,
         const float* __restrict__ Vg, float* __restrict__ Og) {
    __shared__ __align__(16) char sm[4 * 64 * APITCH];
    const uint32_t sb = smem_u32(sm);

    const int tid  = threadIdx.x;
    const int lane = tid & 31;
    const int w    = tid >> 5;
    const int b    = blockIdx.y >> 4;
    const int h    = blockIdx.y & 15;
    const int q0   = blockIdx.x * 128;

    const float* Qb = Qg + (size_t)b * TT  * DD + h * HDIM;
    const float* Kb = Kg + (size_t)b * TKK * DD + h * HDIM;
    const float* Vb = Vg + (size_t)b * TKK * DD + h * HDIM;

    // ---- stage Q (128x64 fp32 -> hi/lo bf16) into the 4 buffers ----
    {
        const int row = tid >> 1;            // 0..127
        const int seg = (tid & 1) * 32;      // fp32 col base
        const float* pq = Qb + (size_t)(q0 + row) * DD + seg;
        const uint32_t bhi = (row < 64) ? A_SKH : A_SVH;
        const uint32_t blo = (row < 64) ? A_SKL : A_SVL;
        const uint32_t ro  = (uint32_t)((row & 63) * APITCH);
#pragma unroll
        for (int p = 0; p < 4; p++) {
            float4 x0 = ((const float4*)pq)[p * 2];
            float4 x1 = ((const float4*)pq)[p * 2 + 1];
            uint4 hh, ll;
            split8(x0, x1, hh, ll);
            *(uint4*)(sm + bhi + ro + (seg + p * 8) * 2) = hh;
            *(uint4*)(sm + blo + ro + (seg + p * 8) * 2) = ll;
        }
    }
    __syncthreads();

    // ---- Q fragments (persist across key loop) ----
    uint32_t qfh[4][4], qfl[4][4];
    {
        const uint32_t bhi = (w < 4) ? A_SKH : A_SVH;
        const uint32_t blo = (w < 4) ? A_SKL : A_SVL;
        const uint32_t ao = (uint32_t)(((w * 16 + (lane & 15)) & 63) * APITCH
                                       + (lane >> 4) * 16);
#pragma unroll
        for (int ks = 0; ks < 4; ks++) {
            ldm4(qfh[ks], sb + bhi + ao + ks * 32);
            ldm4(qfl[ks], sb + blo + ao + ks * 32);
        }
    }

    float oacc[8][4];
#pragma unroll
    for (int nt = 0; nt < 8; nt++)
#pragma unroll
        for (int t = 0; t < 4; t++) oacc[nt][t] = 0.f;
    float m0 = -1e30f, m1 = -1e30f, l0 = 0.f, l1 = 0.f;

    const int nkb = ((q0 + 127) / 3) / 64 + 1;   // <= 16

    const uint32_t kfo = (uint32_t)((((lane >> 4) << 3) + (lane & 7)) * APITCH
                                    + ((lane >> 3) & 1) * 16);
    const uint32_t vfo = (uint32_t)(((((lane >> 3) & 1) * 8) + (lane & 7)) * APITCH
                                    + ((lane >> 4) & 1) * 16);
    const int rq = lane >> 2;          // row within warp m16 (0..7)
    const int cq = (lane & 3) * 2;     // col pair base
    const int qg0 = q0 + w * 16 + rq;
    const int qg1 = qg0 + 8;

    for (int kb = 0; kb < nkb; kb++) {
        __syncthreads();   // prior-tile ldmatrix complete before overwrite
        const int kbase = kb * 64;
        {
            const int row = tid >> 2;            // 0..63
            const int seg = (tid & 3) * 16;      // fp32 col base
            const float* pk = Kb + (size_t)(kbase + row) * DD + seg;
            const float* pv = Vb + (size_t)(kbase + row) * DD + seg;
            const uint32_t ro = (uint32_t)(row * APITCH + seg * 2);
#pragma unroll
            for (int p = 0; p < 2; p++) {
                float4 x0 = ((const float4*)pk)[p * 2];
                float4 x1 = ((const float4*)pk)[p * 2 + 1];
                uint4 hh, ll;
                split8(x0, x1, hh, ll);
                *(uint4*)(sm + A_SKH + ro + p * 16) = hh;
                *(uint4*)(sm + A_SKL + ro + p * 16) = ll;
                float4 y0 = ((const float4*)pv)[p * 2];
                float4 y1 = ((const float4*)pv)[p * 2 + 1];
                split8(y0, y1, hh, ll);
                *(uint4*)(sm + A_SVH + ro + p * 16) = hh;
                *(uint4*)(sm + A_SVL + ro + p * 16) = ll;
            }
        }
        __syncthreads();

        // ---- S = Q K^T ----
        float sacc[8][4];
#pragma unroll
        for (int nt = 0; nt < 8; nt++)
#pragma unroll
            for (int t = 0; t < 4; t++) sacc[nt][t] = 0.f;

#pragma unroll
        for (int ks = 0; ks < 4; ks++) {
#pragma unroll
            for (int pi = 0; pi < 4; pi++) {
                uint32_t kh[4], kl[4];
                const uint32_t base = (uint32_t)(pi * 16 * APITCH) + kfo + ks * 32;
                ldm4(kh, sb + A_SKH + base);
                ldm4(kl, sb + A_SKL + base);
                mma16816(sacc[2 * pi],     qfh[ks], kh[0], kh[1]);
                mma16816(sacc[2 * pi],     qfh[ks], kl[0], kl[1]);
                mma16816(sacc[2 * pi],     qfl[ks], kh[0], kh[1]);
                mma16816(sacc[2 * pi + 1], qfh[ks], kh[2], kh[3]);
                mma16816(sacc[2 * pi + 1], qfh[ks], kl[2], kl[3]);
                mma16816(sacc[2 * pi + 1], qfl[ks], kh[2], kh[3]);
            }
        }

        // ---- mask + scale + online softmax (rows private to warp) ----
        float tm0 = -1e30f, tm1 = -1e30f;
#pragma unroll
        for (int nt = 0; nt < 8; nt++) {
            const int kg0 = kbase + nt * 8 + cq;
            const int kg1 = kg0 + 1;
            float s00 = (3 * kg0 <= qg0) ? sacc[nt][0] * 0.125f : -1e30f;
            float s01 = (3 * kg1 <= qg0) ? sacc[nt][1] * 0.125f : -1e30f;
            float s10 = (3 * kg0 <= qg1) ? sacc[nt][2] * 0.125f : -1e30f;
            float s11 = (3 * kg1 <= qg1) ? sacc[nt][3] * 0.125f : -1e30f;
            sacc[nt][0] = s00; sacc[nt][1] = s01;
            sacc[nt][2] = s10; sacc[nt][3] = s11;
            tm0 = fmaxf(tm0, fmaxf(s00, s01));
            tm1 = fmaxf(tm1, fmaxf(s10, s11));
        }
        tm0 = fmaxf(tm0, __shfl_xor_sync(0xffffffffu, tm0, 1));
        tm0 = fmaxf(tm0, __shfl_xor_sync(0xffffffffu, tm0, 2));
        tm1 = fmaxf(tm1, __shfl_xor_sync(0xffffffffu, tm1, 1));
        tm1 = fmaxf(tm1, __shfl_xor_sync(0xffffffffu, tm1, 2));

        const float mn0 = fmaxf(m0, tm0);
        const float mn1 = fmaxf(m1, tm1);
        const float al0 = __expf(m0 - mn0);
        const float al1 = __expf(m1 - mn1);
        float ps0 = 0.f, ps1 = 0.f;
#pragma unroll
        for (int nt = 0; nt < 8; nt++) {
            float p00 = __expf(sacc[nt][0] - mn0);
            float p01 = __expf(sacc[nt][1] - mn0);
            float p10 = __expf(sacc[nt][2] - mn1);
            float p11 = __expf(sacc[nt][3] - mn1);
            sacc[nt][0] = p00; sacc[nt][1] = p01;
            sacc[nt][2] = p10; sacc[nt][3] = p11;
            ps0 += p00 + p01;
            ps1 += p10 + p11;
        }
        ps0 += __shfl_xor_sync(0xffffffffu, ps0, 1);
        ps0 += __shfl_xor_sync(0xffffffffu, ps0, 2);
        ps1 += __shfl_xor_sync(0xffffffffu, ps1, 1);
        ps1 += __shfl_xor_sync(0xffffffffu, ps1, 2);
        l0 = l0 * al0 + ps0;
        l1 = l1 * al1 + ps1;
        m0 = mn0; m1 = mn1;

#pragma unroll
        for (int nt = 0; nt < 8; nt++) {
            oacc[nt][0] *= al0; oacc[nt][1] *= al0;
            oacc[nt][2] *= al1; oacc[nt][3] *= al1;
        }

        // ---- O += P V  (P fragments built from sacc, V via ldmatrix.trans) ----
#pragma unroll
        for (int ks = 0; ks < 4; ks++) {
            uint32_t pah[4], pal[4];
            split2(sacc[2 * ks][0],     sacc[2 * ks][1],     pah[0], pal[0]);
            split2(sacc[2 * ks][2],     sacc[2 * ks][3],     pah[1], pal[1]);
            split2(sacc[2 * ks + 1][0], sacc[2 * ks + 1][1], pah[2], pal[2]);
            split2(sacc[2 * ks + 1][2], sacc[2 * ks + 1][3], pah[3], pal[3]);
#pragma unroll
            for (int di = 0; di < 4; di++) {
                uint32_t vh[4], vl[4];
                const uint32_t base = (uint32_t)(ks * 16 * APITCH) + vfo + di * 32;
                ldm4t(vh, sb + A_SVH + base);
                ldm4t(vl, sb + A_SVL + base);
                mma16816(oacc[2 * di],     pah, vh[0], vh[1]);
                mma16816(oacc[2 * di],     pah, vl[0], vl[1]);
                mma16816(oacc[2 * di],     pal, vh[0], vh[1]);
                mma16816(oacc[2 * di + 1], pah, vh[2], vh[3]);
                mma16816(oacc[2 * di + 1], pah, vl[2], vl[3]);
                mma16816(oacc[2 * di + 1], pal, vh[2], vh[3]);
            }
        }
    }

    // ---- normalize + write ----
    const float il0 = 1.0f / l0;
    const float il1 = 1.0f / l1;
    float* po = Og + ((size_t)b * TT + qg0) * DD + h * HDIM;
#pragma unroll
    for (int nt = 0; nt < 8; nt++) {
        const int col = nt * 8 + cq;
        *(float2*)(po + col) =
            make_float2(oacc[nt][0] * il0, oacc[nt][1] * il0);
        *(float2*)(po + (size_t)8 * DD + col) =
            make_float2(oacc[nt][2] * il1, oacc[nt][3] * il1);
    }
}

// ------------------------------------------------------------------
extern "C" void kernel_launch(void* const* d_in, const int* in_sizes, int n_in,
                              void* d_out, int out_size) {
    const float* x     = (const float*)d_in[0];
    const float* Wq    = (const float*)d_in[1];
    const float* Wk    = (const float*)d_in[2];
    const float* Wv    = (const float*)d_in[3];
    const float* Wo    = (const float*)d_in[4];
    const float* bo    = (const float*)d_in[5];
    const float* Wconv = (const float*)d_in[6];
    float* out = (float*)d_out;

    float *wt, *ktmp, *q, *k, *v, *att;
    cudaGetSymbolAddress((void**)&wt,   g_wt);
    cudaGetSymbolAddress((void**)&ktmp, g_ktmp);
    cudaGetSymbolAddress((void**)&q,    g_q);
    cudaGetSymbolAddress((void**)&k,    g_k);
    cudaGetSymbolAddress((void**)&v,    g_v);
    cudaGetSymbolAddress((void**)&att,  g_att);

    cudaFuncSetAttribute(mma_gemm<0, false>,
                         cudaFuncAttributeMaxDynamicSharedMemorySize, G_SMEM);
    cudaFuncSetAttribute(mma_gemm<1, false>,
                         cudaFuncAttributeMaxDynamicSharedMemorySize, G_SMEM);
    cudaFuncSetAttribute(mma_gemm<0, true>,
                         cudaFuncAttributeMaxDynamicSharedMemorySize, G_SMEM);

    conv_w_transpose<<<(1024 * 1024 * 3 + 255) / 256, 256>>>(Wconv, wt);
    copy_first_rows<<<16, 256>>>(x, ktmp);
    mma_gemm<1, false><<<dim3(8, 32), 512, G_SMEM>>>(x, wt, nullptr, ktmp, 4096, 1024, 3072);
    mma_gemm<0, false><<<dim3(8, 96), 512, G_SMEM>>>(x, Wq, nullptr, q, BB * TT, 1024, 1024);
    mma_gemm<0, false><<<dim3(8, 33), 512, G_SMEM>>>(ktmp, Wk, nullptr, k, BB * TKK, 1024, 1024);
    mma_gemm<0, false><<<dim3(8, 33), 512, G_SMEM>>>(ktmp, Wv, nullptr, v, BB * TKK, 1024, 1024);
    attn_mma<<<dim3(24, 64), 256>>>(q, k, v, att);
    mma_gemm<0, true><<<dim3(8, 96), 512, G_SMEM>>>(att, Wo, bo, out, BB * TT, 1024, 1024);
}

// round 6
// speedup vs baseline: 2.6254x; 1.0361x over previous
#include <cuda_runtime.h>
#include <cuda_bf16.h>
#include <math.h>
#include <stdint.h>

// Problem constants
#define BB   4
#define TT   3072
#define DD   1024
#define HH   16
#define HDIM 64
#define TKK  1025   // 1 + 3072/3

// -------- scratch (no cudaMalloc allowed) --------
__device__ float g_wt  [1024 * 3072];
__device__ float g_ktmp[BB * TKK * DD];
__device__ float g_q   [BB * TT  * DD];
__device__ float g_k   [BB * TKK * DD];
__device__ float g_v   [BB * TKK * DD];
__device__ float g_att [BB * TT  * DD];

static __device__ __forceinline__ uint32_t smem_u32(const void* p) {
    uint32_t a;
    asm("{ .reg .u64 t; cvta.to.shared.u64 t, %1; cvt.u32.u64 %0, t; }"
        : "=r"(a) : "l"(p));
    return a;
}

static __device__ __forceinline__ void mma16816(
    float* d, const uint32_t* a, uint32_t b0, uint32_t b1)
{
    asm volatile(
        "mma.sync.aligned.m16n8k16.row.col.f32.bf16.bf16.f32 "
        "{%0,%1,%2,%3}, {%4,%5,%6,%7}, {%8,%9}, {%0,%1,%2,%3};"
        : "+f"(d[0]), "+f"(d[1]), "+f"(d[2]), "+f"(d[3])
        : "r"(a[0]), "r"(a[1]), "r"(a[2]), "r"(a[3]), "r"(b0), "r"(b1));
}

static __device__ __forceinline__ void ldm4(uint32_t* r, uint32_t addr) {
    asm volatile(
        "ldmatrix.sync.aligned.m8n8.x4.shared.b16 {%0,%1,%2,%3}, [%4];"
        : "=r"(r[0]), "=r"(r[1]), "=r"(r[2]), "=r"(r[3]) : "r"(addr));
}

static __device__ __forceinline__ void ldm4t(uint32_t* r, uint32_t addr) {
    asm volatile(
        "ldmatrix.sync.aligned.m8n8.x4.trans.shared.b16 {%0,%1,%2,%3}, [%4];"
        : "=r"(r[0]), "=r"(r[1]), "=r"(r[2]), "=r"(r[3]) : "r"(addr));
}

static __device__ __forceinline__ uint32_t packbf2(float x, float y) {
    __nv_bfloat162 t = __floats2bfloat162_rn(x, y);
    return *(uint32_t*)&t;
}

static __device__ __forceinline__ void split8(float4 a, float4 b, uint4& hi, uint4& lo) {
    float f[8] = {a.x, a.y, a.z, a.w, b.x, b.y, b.z, b.w};
    float r[8];
#pragma unroll
    for (int i = 0; i < 8; i++) {
        __nv_bfloat16 h = __float2bfloat16_rn(f[i]);
        r[i] = f[i] - __bfloat162float(h);
    }
    hi.x = packbf2(f[0], f[1]); hi.y = packbf2(f[2], f[3]);
    hi.z = packbf2(f[4], f[5]); hi.w = packbf2(f[6], f[7]);
    lo.x = packbf2(r[0], r[1]); lo.y = packbf2(r[2], r[3]);
    lo.z = packbf2(r[4], r[5]); lo.w = packbf2(r[6], r[7]);
}

static __device__ __forceinline__ void split2(float a, float b, uint32_t& hi, uint32_t& lo) {
    __nv_bfloat16 ha = __float2bfloat16_rn(a);
    __nv_bfloat16 hb = __float2bfloat16_rn(b);
    hi = ((uint32_t)__bfloat16_as_ushort(hb) << 16) | (uint32_t)__bfloat16_as_ushort(ha);
    lo = packbf2(a - __bfloat162float(ha), b - __bfloat162float(hb));
}

// ================= misc prep kernels =================
__global__ void conv_w_transpose(const float* __restrict__ W, float* __restrict__ out) {
    int idx = blockIdx.x * 256 + threadIdx.x;
    if (idx < 1024 * 1024 * 3) {
        int kw = idx % 3;
        int i  = (idx / 3) & 1023;
        int o  = idx / 3072;
        out[o * 3072 + kw * 1024 + i] = W[idx];
    }
}

__global__ void copy_first_rows(const float* __restrict__ x, float* __restrict__ ktmp) {
    int idx = blockIdx.x * 256 + threadIdx.x;
    int b = idx >> 10, d = idx & 1023;
    ktmp[(size_t)b * TKK * DD + d] = x[(size_t)b * TT * DD + d];
}

// ================================================================
// GEMM via mma.sync bf16-split, DOUBLE-BUFFERED smem.
// C[m,n] = sum_k A[m,k]*W[n,k] (+bias). Tile 128x128, K chunk 64.
// 512 threads = 16 warps (4x4), warp tile 32x32.
// Two stages of (Ahi,Alo,Bhi,Blo), each 128x144B.
// Loop: LDG c+1 -> mma on stage(c) -> convert+STS stage(c+1) -> sync.
// ================================================================
#define GPITCH 144
#define GSTAGE (4 * 128 * GPITCH)          // 73728 bytes per stage
#define GT_AHI 0
#define GT_ALO (128 * GPITCH)
#define GT_BHI (2 * 128 * GPITCH)
#define GT_BLO (3 * 128 * GPITCH)
#define G_SMEM (2 * GSTAGE)                // 147456 bytes

template <int OUT_MODE, bool HAS_BIAS>
__global__ void __launch_bounds__(512)
mma_gemm(const float* __restrict__ A, const float* __restrict__ W,
         const float* __restrict__ bias, float* __restrict__ C,
         int M, int N, int K) {
    extern __shared__ __align__(16) char smem[];
    const uint32_t sb = smem_u32(smem);

    const int tid  = threadIdx.x;
    const int lane = tid & 31;
    const int warp = tid >> 5;
    const int wm   = warp >> 2;
    const int wn   = warp & 3;
    const int bm   = blockIdx.y * 128;
    const int bn   = blockIdx.x * 128;

    int rowP[2], kcP[2];
#pragma unroll
    for (int s = 0; s < 2; s++) {
        int p = s * 512 + tid;
        rowP[s] = p >> 3;
        kcP[s]  = (p & 7) * 8;
    }

    uint32_t aoff[2], boff[2];
#pragma unroll
    for (int mi = 0; mi < 2; mi++) {
        int rowA = wm * 32 + mi * 16 + (lane & 15);
        aoff[mi] = (uint32_t)(rowA * GPITCH + ((lane >> 4) * 8) * 2);
    }
#pragma unroll
    for (int pi = 0; pi < 2; pi++) {
        int rowB = wn * 32 + pi * 16 + ((lane >> 4) << 3) + (lane & 7);
        boff[pi] = (uint32_t)(rowB * GPITCH + (((lane >> 3) & 1) * 8) * 2);
    }

    float acc[2][4][4];
#pragma unroll
    for (int mi = 0; mi < 2; mi++)
#pragma unroll
        for (int ni = 0; ni < 4; ni++)
#pragma unroll
            for (int t = 0; t < 4; t++) acc[mi][ni][t] = 0.f;

    const int nc = K >> 6;
    float4 a4[4], b4[4];

    // ---- prologue: LDG chunk 0, convert+STS to stage 0 ----
#pragma unroll
    for (int s = 0; s < 2; s++) {
        int ar = bm + rowP[s]; ar = ar < M ? ar : M - 1;
        const float* pa = A + (size_t)ar * K + kcP[s];
        a4[2 * s] = *(const float4*)pa; a4[2 * s + 1] = *(const float4*)(pa + 4);
        const float* pb = W + (size_t)(bn + rowP[s]) * K + kcP[s];
        b4[2 * s] = *(const float4*)pb; b4[2 * s + 1] = *(const float4*)(pb + 4);
    }
#pragma unroll
    for (int s = 0; s < 2; s++) {
        const uint32_t off = (uint32_t)(rowP[s] * GPITCH + kcP[s] * 2);
        uint4 h, l;
        split8(a4[2 * s], a4[2 * s + 1], h, l);
        *(uint4*)(smem + GT_AHI + off) = h;
        *(uint4*)(smem + GT_ALO + off) = l;
        split8(b4[2 * s], b4[2 * s + 1], h, l);
        *(uint4*)(smem + GT_BHI + off) = h;
        *(uint4*)(smem + GT_BLO + off) = l;
    }
    __syncthreads();

    for (int c = 0; c < nc; c++) {
        const uint32_t st  = (uint32_t)((c & 1) ? GSTAGE : 0);
        const uint32_t stn = (uint32_t)((c & 1) ? 0 : GSTAGE);

        // LDG next chunk early (latency hidden under MMA)
        if (c + 1 < nc) {
            const int kb = (c + 1) << 6;
#pragma unroll
            for (int s = 0; s < 2; s++) {
                int ar = bm + rowP[s]; ar = ar < M ? ar : M - 1;
                const float* pa = A + (size_t)ar * K + kb + kcP[s];
                a4[2 * s] = *(const float4*)pa; a4[2 * s + 1] = *(const float4*)(pa + 4);
                const float* pb = W + (size_t)(bn + rowP[s]) * K + kb + kcP[s];
                b4[2 * s] = *(const float4*)pb; b4[2 * s + 1] = *(const float4*)(pb + 4);
            }
        }

        // MMA on current stage
#pragma unroll
        for (int kk = 0; kk < 4; kk++) {
            const uint32_t ko = (uint32_t)(kk * 32);
            uint32_t ah[2][4], al[2][4], bh[2][4], bl[2][4];
            ldm4(ah[0], sb + st + GT_AHI + aoff[0] + ko);
            ldm4(ah[1], sb + st + GT_AHI + aoff[1] + ko);
            ldm4(bh[0], sb + st + GT_BHI + boff[0] + ko);
            ldm4(bh[1], sb + st + GT_BHI + boff[1] + ko);
            ldm4(al[0], sb + st + GT_ALO + aoff[0] + ko);
            ldm4(al[1], sb + st + GT_ALO + aoff[1] + ko);
            ldm4(bl[0], sb + st + GT_BLO + boff[0] + ko);
            ldm4(bl[1], sb + st + GT_BLO + boff[1] + ko);
#pragma unroll
            for (int mi = 0; mi < 2; mi++)
#pragma unroll
                for (int ni = 0; ni < 4; ni++) {
                    const int pr = ni >> 1, ix = (ni & 1) * 2;
                    mma16816(acc[mi][ni], ah[mi], bh[pr][ix], bh[pr][ix + 1]);
                    mma16816(acc[mi][ni], ah[mi], bl[pr][ix], bl[pr][ix + 1]);
                    mma16816(acc[mi][ni], al[mi], bh[pr][ix], bh[pr][ix + 1]);
                }
        }

        // convert + STS next chunk into the other stage, then single sync
        if (c + 1 < nc) {
#pragma unroll
            for (int s = 0; s < 2; s++) {
                const uint32_t off = (uint32_t)(rowP[s] * GPITCH + kcP[s] * 2);
                uint4 h, l;
                split8(a4[2 * s], a4[2 * s + 1], h, l);
                *(uint4*)(smem + stn + GT_AHI + off) = h;
                *(uint4*)(smem + stn + GT_ALO + off) = l;
                split8(b4[2 * s], b4[2 * s + 1], h, l);
                *(uint4*)(smem + stn + GT_BHI + off) = h;
                *(uint4*)(smem + stn + GT_BLO + off) = l;
            }
            __syncthreads();
        }
    }

    // epilogue
#pragma unroll
    for (int mi = 0; mi < 2; mi++) {
#pragma unroll
        for (int ni = 0; ni < 4; ni++) {
            const int col = bn + wn * 32 + ni * 8 + (lane & 3) * 2;
            float2 v0 = make_float2(acc[mi][ni][0], acc[mi][ni][1]);
            float2 v1 = make_float2(acc[mi][ni][2], acc[mi][ni][3]);
            if (HAS_BIAS) {
                const float bx = bias[col], by = bias[col + 1];
                v0.x += bx; v0.y += by; v1.x += bx; v1.y += by;
            }
            const int r0 = bm + wm * 32 + mi * 16 + (lane >> 2);
            const int r1 = r0 + 8;
            if (r0 < M) {
                size_t rb;
                if (OUT_MODE == 1) {
                    const int b = r0 >> 10, rr = r0 & 1023;
                    rb = ((size_t)b * TKK + 1 + rr) * (size_t)N;
                } else rb = (size_t)r0 * (size_t)N;
                *(float2*)&C[rb + col] = v0;
            }
            if (r1 < M) {
                size_t rb;
                if (OUT_MODE == 1) {
                    const int b = r1 >> 10, rr = r1 & 1023;
                    rb = ((size_t)b * TKK + 1 + rr) * (size_t)N;
                } else rb = (size_t)r1 * (size_t)N;
                *(float2*)&C[rb + col] = v1;
            }
        }
    }
}

// ================================================================
// Flash attention via mma.sync bf16-split (round-5 proven, unchanged)
// ================================================================
#define APITCH 144
#define A_SKH 0
#define A_SKL (64 * APITCH)
#define A_SVH (2 * 64 * APITCH)
#define A_SVL (3 * 64 * APITCH)

__global__ void __launch_bounds__(256)
attn_mma(const float* __restrict__ Qg, const float* __restrict__ Kg,
         const float* __restrict__ Vg, float* __restrict__ Og) {
    __shared__ __align__(16) char sm[4 * 64 * APITCH];
    const uint32_t sb = smem_u32(sm);

    const int tid  = threadIdx.x;
    const int lane = tid & 31;
    const int w    = tid >> 5;
    const int b    = blockIdx.y >> 4;
    const int h    = blockIdx.y & 15;
    const int q0   = blockIdx.x * 128;

    const float* Qb = Qg + (size_t)b * TT  * DD + h * HDIM;
    const float* Kb = Kg + (size_t)b * TKK * DD + h * HDIM;
    const float* Vb = Vg + (size_t)b * TKK * DD + h * HDIM;

    {
        const int row = tid >> 1;
        const int seg = (tid & 1) * 32;
        const float* pq = Qb + (size_t)(q0 + row) * DD + seg;
        const uint32_t bhi = (row < 64) ? A_SKH : A_SVH;
        const uint32_t blo = (row < 64) ? A_SKL : A_SVL;
        const uint32_t ro  = (uint32_t)((row & 63) * APITCH);
#pragma unroll
        for (int p = 0; p < 4; p++) {
            float4 x0 = ((const float4*)pq)[p * 2];
            float4 x1 = ((const float4*)pq)[p * 2 + 1];
            uint4 hh, ll;
            split8(x0, x1, hh, ll);
            *(uint4*)(sm + bhi + ro + (seg + p * 8) * 2) = hh;
            *(uint4*)(sm + blo + ro + (seg + p * 8) * 2) = ll;
        }
    }
    __syncthreads();

    uint32_t qfh[4][4], qfl[4][4];
    {
        const uint32_t bhi = (w < 4) ? A_SKH : A_SVH;
        const uint32_t blo = (w < 4) ? A_SKL : A_SVL;
        const uint32_t ao = (uint32_t)(((w * 16 + (lane & 15)) & 63) * APITCH
                                       + (lane >> 4) * 16);
#pragma unroll
        for (int ks = 0; ks < 4; ks++) {
            ldm4(qfh[ks], sb + bhi + ao + ks * 32);
            ldm4(qfl[ks], sb + blo + ao + ks * 32);
        }
    }

    float oacc[8][4];
#pragma unroll
    for (int nt = 0; nt < 8; nt++)
#pragma unroll
        for (int t = 0; t < 4; t++) oacc[nt][t] = 0.f;
    float m0 = -1e30f, m1 = -1e30f, l0 = 0.f, l1 = 0.f;

    const int nkb = ((q0 + 127) / 3) / 64 + 1;

    const uint32_t kfo = (uint32_t)((((lane >> 4) << 3) + (lane & 7)) * APITCH
                                    + ((lane >> 3) & 1) * 16);
    const uint32_t vfo = (uint32_t)(((((lane >> 3) & 1) * 8) + (lane & 7)) * APITCH
                                    + ((lane >> 4) & 1) * 16);
    const int rq = lane >> 2;
    const int cq = (lane & 3) * 2;
    const int qg0 = q0 + w * 16 + rq;
    const int qg1 = qg0 + 8;

    for (int kb = 0; kb < nkb; kb++) {
        __syncthreads();
        const int kbase = kb * 64;
        {
            const int row = tid >> 2;
            const int seg = (tid & 3) * 16;
            const float* pk = Kb + (size_t)(kbase + row) * DD + seg;
            const float* pv = Vb + (size_t)(kbase + row) * DD + seg;
            const uint32_t ro = (uint32_t)(row * APITCH + seg * 2);
#pragma unroll
            for (int p = 0; p < 2; p++) {
                float4 x0 = ((const float4*)pk)[p * 2];
                float4 x1 = ((const float4*)pk)[p * 2 + 1];
                uint4 hh, ll;
                split8(x0, x1, hh, ll);
                *(uint4*)(sm + A_SKH + ro + p * 16) = hh;
                *(uint4*)(sm + A_SKL + ro + p * 16) = ll;
                float4 y0 = ((const float4*)pv)[p * 2];
                float4 y1 = ((const float4*)pv)[p * 2 + 1];
                split8(y0, y1, hh, ll);
                *(uint4*)(sm + A_SVH + ro + p * 16) = hh;
                *(uint4*)(sm + A_SVL + ro + p * 16) = ll;
            }
        }
        __syncthreads();

        float sacc[8][4];
#pragma unroll
        for (int nt = 0; nt < 8; nt++)
#pragma unroll
            for (int t = 0; t < 4; t++) sacc[nt][t] = 0.f;

#pragma unroll
        for (int ks = 0; ks < 4; ks++) {
#pragma unroll
            for (int pi = 0; pi < 4; pi++) {
                uint32_t kh[4], kl[4];
                const uint32_t base = (uint32_t)(pi * 16 * APITCH) + kfo + ks * 32;
                ldm4(kh, sb + A_SKH + base);
                ldm4(kl, sb + A_SKL + base);
                mma16816(sacc[2 * pi],     qfh[ks], kh[0], kh[1]);
                mma16816(sacc[2 * pi],     qfh[ks], kl[0], kl[1]);
                mma16816(sacc[2 * pi],     qfl[ks], kh[0], kh[1]);
                mma16816(sacc[2 * pi + 1], qfh[ks], kh[2], kh[3]);
                mma16816(sacc[2 * pi + 1], qfh[ks], kl[2], kl[3]);
                mma16816(sacc[2 * pi + 1], qfl[ks], kh[2], kh[3]);
            }
        }

        float tm0 = -1e30f, tm1 = -1e30f;
#pragma unroll
        for (int nt = 0; nt < 8; nt++) {
            const int kg0 = kbase + nt * 8 + cq;
            const int kg1 = kg0 + 1;
            float s00 = (3 * kg0 <= qg0) ? sacc[nt][0] * 0.125f : -1e30f;
            float s01 = (3 * kg1 <= qg0) ? sacc[nt][1] * 0.125f : -1e30f;
            float s10 = (3 * kg0 <= qg1) ? sacc[nt][2] * 0.125f : -1e30f;
            float s11 = (3 * kg1 <= qg1) ? sacc[nt][3] * 0.125f : -1e30f;
            sacc[nt][0] = s00; sacc[nt][1] = s01;
            sacc[nt][2] = s10; sacc[nt][3] = s11;
            tm0 = fmaxf(tm0, fmaxf(s00, s01));
            tm1 = fmaxf(tm1, fmaxf(s10, s11));
        }
        tm0 = fmaxf(tm0, __shfl_xor_sync(0xffffffffu, tm0, 1));
        tm0 = fmaxf(tm0, __shfl_xor_sync(0xffffffffu, tm0, 2));
        tm1 = fmaxf(tm1, __shfl_xor_sync(0xffffffffu, tm1, 1));
        tm1 = fmaxf(tm1, __shfl_xor_sync(0xffffffffu, tm1, 2));

        const float mn0 = fmaxf(m0, tm0);
        const float mn1 = fmaxf(m1, tm1);
        const float al0 = __expf(m0 - mn0);
        const float al1 = __expf(m1 - mn1);
        float ps0 = 0.f, ps1 = 0.f;
#pragma unroll
        for (int nt = 0; nt < 8; nt++) {
            float p00 = __expf(sacc[nt][0] - mn0);
            float p01 = __expf(sacc[nt][1] - mn0);
            float p10 = __expf(sacc[nt][2] - mn1);
            float p11 = __expf(sacc[nt][3] - mn1);
            sacc[nt][0] = p00; sacc[nt][1] = p01;
            sacc[nt][2] = p10; sacc[nt][3] = p11;
            ps0 += p00 + p01;
            ps1 += p10 + p11;
        }
        ps0 += __shfl_xor_sync(0xffffffffu, ps0, 1);
        ps0 += __shfl_xor_sync(0xffffffffu, ps0, 2);
        ps1 += __shfl_xor_sync(0xffffffffu, ps1, 1);
        ps1 += __shfl_xor_sync(0xffffffffu, ps1, 2);
        l0 = l0 * al0 + ps0;
        l1 = l1 * al1 + ps1;
        m0 = mn0; m1 = mn1;

#pragma unroll
        for (int nt = 0; nt < 8; nt++) {
            oacc[nt][0] *= al0; oacc[nt][1] *= al0;
            oacc[nt][2] *= al1; oacc[nt][3] *= al1;
        }

#pragma unroll
        for (int ks = 0; ks < 4; ks++) {
            uint32_t pah[4], pal[4];
            split2(sacc[2 * ks][0],     sacc[2 * ks][1],     pah[0], pal[0]);
            split2(sacc[2 * ks][2],     sacc[2 * ks][3],     pah[1], pal[1]);
            split2(sacc[2 * ks + 1][0], sacc[2 * ks + 1][1], pah[2], pal[2]);
            split2(sacc[2 * ks + 1][2], sacc[2 * ks + 1][3], pah[3], pal[3]);
#pragma unroll
            for (int di = 0; di < 4; di++) {
                uint32_t vh[4], vl[4];
                const uint32_t base = (uint32_t)(ks * 16 * APITCH) + vfo + di * 32;
                ldm4t(vh, sb + A_SVH + base);
                ldm4t(vl, sb + A_SVL + base);
                mma16816(oacc[2 * di],     pah, vh[0], vh[1]);
                mma16816(oacc[2 * di],     pah, vl[0], vl[1]);
                mma16816(oacc[2 * di],     pal, vh[0], vh[1]);
                mma16816(oacc[2 * di + 1], pah, vh[2], vh[3]);
                mma16816(oacc[2 * di + 1], pah, vl[2], vl[3]);
                mma16816(oacc[2 * di + 1], pal, vh[2], vh[3]);
            }
        }
    }

    const float il0 = 1.0f / l0;
    const float il1 = 1.0f / l1;
    float* po = Og + ((size_t)b * TT + qg0) * DD + h * HDIM;
#pragma unroll
    for (int nt = 0; nt < 8; nt++) {
        const int col = nt * 8 + cq;
        *(float2*)(po + col) =
            make_float2(oacc[nt][0] * il0, oacc[nt][1] * il0);
        *(float2*)(po + (size_t)8 * DD + col) =
            make_float2(oacc[nt][2] * il1, oacc[nt][3] * il1);
    }
}

// ------------------------------------------------------------------
extern "C" void kernel_launch(void* const* d_in, const int* in_sizes, int n_in,
                              void* d_out, int out_size) {
    const float* x     = (const float*)d_in[0];
    const float* Wq    = (const float*)d_in[1];
    const float* Wk    = (const float*)d_in[2];
    const float* Wv    = (const float*)d_in[3];
    const float* Wo    = (const float*)d_in[4];
    const float* bo    = (const float*)d_in[5];
    const float* Wconv = (const float*)d_in[6];
    float* out = (float*)d_out;

    float *wt, *ktmp, *q, *k, *v, *att;
    cudaGetSymbolAddress((void**)&wt,   g_wt);
    cudaGetSymbolAddress((void**)&ktmp, g_ktmp);
    cudaGetSymbolAddress((void**)&q,    g_q);
    cudaGetSymbolAddress((void**)&k,    g_k);
    cudaGetSymbolAddress((void**)&v,    g_v);
    cudaGetSymbolAddress((void**)&att,  g_att);

    cudaFuncSetAttribute(mma_gemm<0, false>,
                         cudaFuncAttributeMaxDynamicSharedMemorySize, G_SMEM);
    cudaFuncSetAttribute(mma_gemm<1, false>,
                         cudaFuncAttributeMaxDynamicSharedMemorySize, G_SMEM);
    cudaFuncSetAttribute(mma_gemm<0, true>,
                         cudaFuncAttributeMaxDynamicSharedMemorySize, G_SMEM);

    conv_w_transpose<<<(1024 * 1024 * 3 + 255) / 256, 256>>>(Wconv, wt);
    copy_first_rows<<<16, 256>>>(x, ktmp);
    mma_gemm<1, false><<<dim3(8, 32), 512, G_SMEM>>>(x, wt, nullptr, ktmp, 4096, 1024, 3072);
    mma_gemm<0, false><<<dim3(8, 96), 512, G_SMEM>>>(x, Wq, nullptr, q, BB * TT, 1024, 1024);
    mma_gemm<0, false><<<dim3(8, 33), 512, G_SMEM>>>(ktmp, Wk, nullptr, k, BB * TKK, 1024, 1024);
    mma_gemm<0, false><<<dim3(8, 33), 512, G_SMEM>>>(ktmp, Wv, nullptr, v, BB * TKK, 1024, 1024);
    attn_mma<<<dim3(24, 64), 256>>>(q, k, v, att);
    mma_gemm<0, true><<<dim3(8, 96), 512, G_SMEM>>>(att, Wo, bo, out, BB * TT, 1024, 1024);
}